// round 17
// baseline (speedup 1.0000x reference)
#include <cuda_runtime.h>
#include <cuda_bf16.h>
#include <math.h>
#include <stdint.h>

// Problem constants
#define BB 2048
#define KK 64
#define DIN 768
#define CF 64
#define MROWS (BB*KK)
#define SHARPNESS 1048576.0f
#define NCH 12            // K chunks of 64
#define CAND_TH 0.015f    // approx-score gap threshold for refinement
#define RCAP 32768

// ---------------- scratch ----------------
__device__ float g_xfeat[BB*CF];
__device__ float g_exact[MROWS];
__device__ int   g_list[MROWS];
__device__ int   g_count;
__device__ float g_WphiT[DIN*CF];        // Wphi^T [k][f]
__device__ float g_WthetaT[DIN*CF];      // Wtheta^T [k][f]
__device__ float g_upart[4][RCAP*64];
__device__ float g_Wc[9];                // Wo @ Wg
__device__ float g_bc[3];                // Wo @ bg + bo
__device__ __align__(16) uint2 g_Bfrag[NCH*4*8*32];   // bf16 B fragments, L2-resident

// ---------------- helpers ----------------
__device__ __forceinline__ void cpa16(void* smem, const void* g) {
    unsigned s = (unsigned)__cvta_generic_to_shared(smem);
    asm volatile("cp.async.cg.shared.global [%0], [%1], 16;" :: "r"(s), "l"(g));
}
#define CP_COMMIT() asm volatile("cp.async.commit_group;")
#define CP_WAIT1()  asm volatile("cp.async.wait_group 1;" ::: "memory")

__device__ __forceinline__ uint32_t cvt_hi(float a0, float a1) {
    uint32_t hp;
    asm("cvt.rn.satfinite.bf16x2.f32 %0, %1, %2;" : "=r"(hp) : "f"(a1), "f"(a0));
    return hp;
}

__device__ __forceinline__ void mma_bf16(float* d, const uint32_t* a, uint32_t b0, uint32_t b1) {
    asm volatile("mma.sync.aligned.m16n8k16.row.col.f32.bf16.bf16.f32 "
        "{%0,%1,%2,%3}, {%4,%5,%6,%7}, {%8,%9}, {%0,%1,%2,%3};"
        : "+f"(d[0]), "+f"(d[1]), "+f"(d[2]), "+f"(d[3])
        : "r"(a[0]), "r"(a[1]), "r"(a[2]), "r"(a[3]), "r"(b0), "r"(b1));
}

// ---------------- kernel EF: fused weight preprocessing ----------------
// [0,48): Wphi bf16 fragments; [48,240): WphiT (+count reset); [240,432): WthetaT; 432: Wc/bc
__global__ void kernEF(const float* __restrict__ Wphi, const float* __restrict__ Wtheta,
                       const float* __restrict__ Wg, const float* __restrict__ bg,
                       const float* __restrict__ Wo, const float* __restrict__ bo) {
    int bid = blockIdx.x, tid = threadIdx.x;
    if (bid < 48) {
        int idx = bid * 256 + tid;
        int lane = idx & 31;
        int t = idx >> 5;
        int nt = t & 7, ks = (t >> 3) & 3, c = t >> 5;
        int g = lane >> 2, tig = lane & 3;
        int n = nt * 8 + g;
        int k0 = c * 64 + ks * 16 + 2 * tig;
        const float* wr = Wphi + n * DIN + k0;
        uint32_t h01 = cvt_hi(wr[0], wr[1]);
        uint32_t h23 = cvt_hi(wr[8], wr[9]);
        g_Bfrag[((c * 4 + ks) * 8 + nt) * 32 + lane] = make_uint2(h01, h23);
    } else if (bid < 240) {
        int o = (bid - 48) * 256 + tid;
        if (o == 0) g_count = 0;
        int k = o >> 6, f = o & 63;
        g_WphiT[o] = Wphi[f * DIN + k];
    } else if (bid < 432) {
        int o = (bid - 240) * 256 + tid;
        int k = o >> 6, f = o & 63;
        g_WthetaT[o] = Wtheta[f * DIN + k];
    } else {
        if (tid < 9) {
            int o = tid / 3, c = tid % 3;
            g_Wc[tid] = Wo[o * 3 + 0] * Wg[0 * 3 + c] + Wo[o * 3 + 1] * Wg[1 * 3 + c]
                      + Wo[o * 3 + 2] * Wg[2 * 3 + c];
        } else if (tid < 12) {
            int o = tid - 9;
            g_bc[o] = Wo[o * 3 + 0] * bg[0] + Wo[o * 3 + 1] * bg[1] + Wo[o * 3 + 2] * bg[2] + bo[o];
        }
    }
}

// ---------------- kernel A: x_feat, WthetaT chunk-staged, 16 b/block ----------------
__global__ void __launch_bounds__(256) kernA(const float* __restrict__ xim,
                                             const float* __restrict__ btheta) {
    __shared__ __align__(16) float xs[16 * DIN];     // 48KB
    __shared__ __align__(16) float Wsm[2][64 * 64];  // 32KB
    __shared__ float wred[16][2];
    int tid = threadIdx.x;
    int b0 = blockIdx.x * 16;

    auto stageW = [&](int c, int s) {
        const char* src = (const char*)(g_WthetaT + c * 4096) + tid * 64;
        char* dst = (char*)&Wsm[s][0] + tid * 64;
#pragma unroll
        for (int i = 0; i < 4; i++) cpa16(dst + 16 * i, src + 16 * i);
        CP_COMMIT();
    };

    stageW(0, 0); stageW(1, 1);
    {
        const float4* src = (const float4*)(xim + (size_t)b0 * DIN);
        float4* d4 = (float4*)xs;
#pragma unroll
        for (int j = 0; j < 12; j++) d4[tid + 256 * j] = src[tid + 256 * j];
    }

    int f = tid & 63, q = tid >> 6;
    float acc[4] = {0.f, 0.f, 0.f, 0.f};
    for (int c = 0; c < NCH; c++) {
        const int s = c & 1;
        CP_WAIT1();
        __syncthreads();
        const float* Ws = &Wsm[s][0];
#pragma unroll 8
        for (int kk = 0; kk < 64; kk += 2) {
            float w0 = Ws[kk * 64 + f];
            float w1 = Ws[(kk + 1) * 64 + f];
#pragma unroll
            for (int j = 0; j < 4; j++) {
                float2 xv = *(const float2*)&xs[(4 * q + j) * DIN + c * 64 + kk];
                acc[j] += w0 * xv.x;
                acc[j] += w1 * xv.y;
            }
        }
        __syncthreads();
        if (c + 2 < NCH) stageW(c + 2, s);
        else CP_COMMIT();
    }
    float bt = btheta[f];
#pragma unroll
    for (int j = 0; j < 4; j++) acc[j] += bt;

    int w = tid >> 5;
    float ss[4];
#pragma unroll
    for (int j = 0; j < 4; j++) {
        ss[j] = acc[j] * acc[j];
#pragma unroll
        for (int o = 1; o < 32; o <<= 1) ss[j] += __shfl_xor_sync(0xffffffffu, ss[j], o);
    }
    if ((tid & 31) == 0) {
#pragma unroll
        for (int j = 0; j < 4; j++) wred[q * 4 + j][w & 1] = ss[j];
    }
    __syncthreads();
#pragma unroll
    for (int j = 0; j < 4; j++) {
        float n = wred[q * 4 + j][0] + wred[q * 4 + j][1];
        g_xfeat[(b0 + 4 * q + j) * CF + f] = acc[j] / fmaxf(sqrtf(n), 1e-12f);
    }
}

// ---------------- kernel B: 1-term bf16 HMMA, bf16 A staging, 3-stage pipeline ----------------
#define AROWB 144               // bf16 row stride in bytes (128 data + 16 pad; conflict-free)
#define S_A  0                  // 3 stages x 128*144 = 55296
#define S_B  55296              // 3 stages x 8192 = 24576
#define S_XF 79872              // 512
#define S_BP 80384              // 256
#define S_SC 80640              // 512
#define SMEMB_TOTAL 81152

__global__ void __launch_bounds__(256, 2) kernB(const float* __restrict__ pim,
                                                const float* __restrict__ bphi) {
    extern __shared__ __align__(16) char smem[];
    char*  Asm = smem + S_A;                         // [3][128*AROWB] bf16
    uint2* Bsm = (uint2*)(smem + S_B);               // [3][1024]
    float* xfsm = (float*)(smem + S_XF);
    float* bpsm = (float*)(smem + S_BP);
    float* scsm = (float*)(smem + S_SC);

    int tid = threadIdx.x, w = tid >> 5, lane = tid & 31;
    int g = lane >> 2, tig = lane & 3;
    int m0 = blockIdx.x * 128;
    if (tid < 128) xfsm[tid] = g_xfeat[m0 + tid];
    else if (tid < 192) bpsm[tid - 128] = bphi[tid - 128];

    float acc[8][4];
#pragma unroll
    for (int nt = 0; nt < 8; nt++)
#pragma unroll
        for (int i = 0; i < 4; i++) acc[nt][i] = 0.f;

    // A staging mapping: thread t -> row r = t>>1, half h = t&1 (cols h*32..h*32+31)
    const int ar = tid >> 1;
    const int ah = tid & 1;
    const float4* asrc = (const float4*)(pim + (size_t)(m0 + ar) * DIN + ah * 32);
    char* adst_base = Asm;   // + stage*128*AROWB + ar*AROWB + ah*64

    auto ldA = [&](int c, float4* av) {
        const float4* s4 = asrc + c * 16;            // c*64 floats
#pragma unroll
        for (int i = 0; i < 8; i++) av[i] = s4[i];
    };
    auto stA = [&](int s, const float4* av) {
        uint32_t pk[16];
#pragma unroll
        for (int i = 0; i < 8; i++) {
            pk[2 * i]     = cvt_hi(av[i].x, av[i].y);
            pk[2 * i + 1] = cvt_hi(av[i].z, av[i].w);
        }
        char* d = adst_base + s * (128 * AROWB) + ar * AROWB + ah * 64;
#pragma unroll
        for (int i = 0; i < 4; i++)
            *(uint4*)(d + 16 * i) = make_uint4(pk[4 * i], pk[4 * i + 1], pk[4 * i + 2], pk[4 * i + 3]);
    };
    auto issueB = [&](int c, int s) {
        const char* bs = (const char*)(g_Bfrag + (size_t)c * 1024) + tid * 32;
        char* bd = (char*)(Bsm + s * 1024) + tid * 32;
        cpa16(bd, bs); cpa16(bd + 16, bs + 16);
        CP_COMMIT();
    };

    // prologue: A chunks 0,1 staged directly; B chunks 0,1 in flight
    {
        float4 av[8];
        ldA(0, av); stA(0, av);
        ldA(1, av); stA(1, av);
    }
    issueB(0, 0); issueB(1, 1);

    for (int c = 0; c < NCH; c++) {
        const int s = c % 3;
        const bool pf = (c + 2 < NCH);
        float4 av[8];
        if (pf) ldA(c + 2, av);          // LDG overlaps B-wait + MMA below
        CP_WAIT1();
        __syncthreads();
        const char* As = Asm + s * (128 * AROWB);
        const uint2* Bs = Bsm + s * 1024;
        const int r0 = 16 * w + g;
#pragma unroll
        for (int ks = 0; ks < 4; ks++) {
            const int kbyte = 32 * ks + 4 * tig;     // (16*ks + 2*tig) bf16 -> bytes
            uint32_t Ah[4];
            Ah[0] = *(const uint32_t*)(As + r0 * AROWB + kbyte);
            Ah[1] = *(const uint32_t*)(As + (r0 + 8) * AROWB + kbyte);
            Ah[2] = *(const uint32_t*)(As + r0 * AROWB + kbyte + 16);
            Ah[3] = *(const uint32_t*)(As + (r0 + 8) * AROWB + kbyte + 16);
#pragma unroll
            for (int nt = 0; nt < 8; nt++) {
                uint2 b = Bs[(ks * 8 + nt) * 32 + lane];
                mma_bf16(acc[nt], Ah, b.x, b.y);
            }
        }
        if (pf) {
            stA((c + 2) % 3, av);        // stage (c+2)%3 free: last read in chunk c-1
            issueB(c + 2, (c + 2) % 3);
        } else {
            CP_COMMIT();                 // keep group accounting uniform
        }
    }

    // Epilogue: u = D + bphi; approx score = dot(xf,u)/max(||u||,1e-12)
    int bi = w >> 2;
    float ps0 = 0.f, pd0 = 0.f, ps1 = 0.f, pd1 = 0.f;
#pragma unroll
    for (int nt = 0; nt < 8; nt++) {
        int col = nt * 8 + 2 * tig;
        float b0 = bpsm[col], b1 = bpsm[col + 1];
        float x0 = xfsm[bi * 64 + col], x1 = xfsm[bi * 64 + col + 1];
        float u;
        u = acc[nt][0] + b0; ps0 += u * u; pd0 += u * x0;
        u = acc[nt][1] + b1; ps0 += u * u; pd0 += u * x1;
        u = acc[nt][2] + b0; ps1 += u * u; pd1 += u * x0;
        u = acc[nt][3] + b1; ps1 += u * u; pd1 += u * x1;
    }
#pragma unroll
    for (int o = 1; o < 4; o <<= 1) {
        ps0 += __shfl_xor_sync(0xffffffffu, ps0, o);
        pd0 += __shfl_xor_sync(0xffffffffu, pd0, o);
        ps1 += __shfl_xor_sync(0xffffffffu, ps1, o);
        pd1 += __shfl_xor_sync(0xffffffffu, pd1, o);
    }
    int lr = 16 * w + g;
    if (tig == 0) {
        scsm[lr]     = pd0 / fmaxf(sqrtf(ps0), 1e-12f);
        scsm[lr + 8] = pd1 / fmaxf(sqrtf(ps1), 1e-12f);
    }
    if (tid < 128) g_exact[m0 + tid] = -1e30f;
    __syncthreads();

    if (w < 2) {
        float s0 = scsm[w * 64 + lane];
        float s1 = scsm[w * 64 + 32 + lane];
        float m = fmaxf(s0, s1);
#pragma unroll
        for (int o = 16; o >= 1; o >>= 1) m = fmaxf(m, __shfl_xor_sync(0xffffffffu, m, o));
        float th = m - CAND_TH;
        int bidx = m0 + w * 64;
        if (s0 >= th) { int pos = atomicAdd(&g_count, 1); if (pos < RCAP) g_list[pos] = bidx + lane; }
        if (s1 >= th) { int pos = atomicAdd(&g_count, 1); if (pos < RCAP) g_list[pos] = bidx + 32 + lane; }
    }
}

// ---------------- kernel RP: partial exact u over one K-part (3 chunks) ----------------
__global__ void __launch_bounds__(256) kernRP(const float* __restrict__ pim) {
    __shared__ __align__(16) float psm[16][192];
    __shared__ __align__(16) float Wsm[2][64 * 64];
    __shared__ int lsm[16];
    int tid = threadIdx.x;
    int part = blockIdx.x & 3;
    int grp = blockIdx.x >> 2;
    int cnt = min(g_count, RCAP);
    const int c0 = part * 3;

    auto stageW = [&](int j, int s) {
        const char* src = (const char*)(g_WphiT + (c0 + j) * 4096) + tid * 64;
        char* dst = (char*)&Wsm[s][0] + tid * 64;
#pragma unroll
        for (int i = 0; i < 4; i++) cpa16(dst + 16 * i, src + 16 * i);
        CP_COMMIT();
    };

    for (int base = grp * 16; base < cnt; base += 256 * 16) {
        __syncthreads();
        if (tid < 16) lsm[tid] = (base + tid < cnt) ? g_list[base + tid] : -1;
        __syncthreads();
        stageW(0, 0); stageW(1, 1);
        int row = tid >> 4, lj = tid & 15;
        if (lsm[row] >= 0) {
            const float4* src = (const float4*)(pim + (size_t)lsm[row] * DIN + part * 192);
            float4* dst = (float4*)&psm[row][0];
#pragma unroll
            for (int jj = 0; jj < 3; jj++) dst[lj + 16 * jj] = src[lj + 16 * jj];
        }

        int f = tid & 63, g = tid >> 6;
        float u[4] = {0.f, 0.f, 0.f, 0.f};
#pragma unroll
        for (int j = 0; j < 3; j++) {
            const int s = j & 1;
            CP_WAIT1();
            __syncthreads();
            const float* Ws = &Wsm[s][0];
#pragma unroll 4
            for (int kk = 0; kk < 64; kk += 4) {
                float w0 = Ws[kk * 64 + f];
                float w1 = Ws[(kk + 1) * 64 + f];
                float w2 = Ws[(kk + 2) * 64 + f];
                float w3 = Ws[(kk + 3) * 64 + f];
#pragma unroll
                for (int q = 0; q < 4; q++) {
                    float4 pv = *(const float4*)&psm[g + 4 * q][j * 64 + kk];
                    u[q] += w0 * pv.x + w1 * pv.y + w2 * pv.z + w3 * pv.w;
                }
            }
            __syncthreads();
            if (j + 2 < 3) stageW(j + 2, s);
            else CP_COMMIT();
        }
#pragma unroll
        for (int q = 0; q < 4; q++) {
            int slot = base + g + 4 * q;
            if (lsm[g + 4 * q] >= 0)
                g_upart[part][(size_t)slot * 64 + f] = u[q];
        }
    }
}

// ---------------- kernel F: finalize exact scores (warp per candidate) ----------------
__global__ void __launch_bounds__(256) kernF(const float* __restrict__ bphi) {
    int tid = threadIdx.x, wid = tid >> 5, lane = tid & 31;
    int cnt = min(g_count, RCAP);
    for (int i = blockIdx.x * 8 + wid; i < cnt; i += gridDim.x * 8) {
        int cand = g_list[i];
        float u0 = bphi[lane], u1 = bphi[lane + 32];
#pragma unroll
        for (int part = 0; part < 4; part++) {
            u0 += g_upart[part][(size_t)i * 64 + lane];
            u1 += g_upart[part][(size_t)i * 64 + lane + 32];
        }
        int b = cand >> 6;
        float xf0 = g_xfeat[b * 64 + lane];
        float xf1 = g_xfeat[b * 64 + lane + 32];
        float ps = u0 * u0 + u1 * u1;
        float pd = u0 * xf0 + u1 * xf1;
#pragma unroll
        for (int o = 16; o >= 1; o >>= 1) {
            ps += __shfl_xor_sync(0xffffffffu, ps, o);
            pd += __shfl_xor_sync(0xffffffffu, pd, o);
        }
        if (lane == 0) g_exact[cand] = pd / fmaxf(sqrtf(ps), 1e-12f);
    }
}

// ---------------- kernel D: softmax + active-list weighted sum + combined mix + blend ----------------
__global__ void __launch_bounds__(192) kernD(const float* __restrict__ x,
                                             const float* __restrict__ p,
                                             const float* __restrict__ sig_scale,
                                             const float* __restrict__ sig_shift,
                                             float* __restrict__ out) {
    __shared__ __align__(16) float buf[DIN];
    __shared__ __align__(16) float wsm[64];
    __shared__ int actsm[64];
    __shared__ float swsm;
    __shared__ int nactsm;
    int tid = threadIdx.x;
    int b = blockIdx.x;

    if (tid < 32) {
        int lane = tid;
        float s0 = g_exact[b * 64 + lane];
        float s1 = g_exact[b * 64 + 32 + lane];
        float t0 = s0 * SHARPNESS, t1 = s1 * SHARPNESS;
        float mraw = fmaxf(s0, s1), mt = fmaxf(t0, t1);
#pragma unroll
        for (int o = 16; o >= 1; o >>= 1) {
            mraw = fmaxf(mraw, __shfl_xor_sync(0xffffffffu, mraw, o));
            mt   = fmaxf(mt,   __shfl_xor_sync(0xffffffffu, mt, o));
        }
        float e0 = expf(t0 - mt), e1 = expf(t1 - mt);
        float sum = e0 + e1;
#pragma unroll
        for (int o = 16; o >= 1; o >>= 1) sum += __shfl_xor_sync(0xffffffffu, sum, o);
        float inv = 1.f / sum;
        float w0 = e0 * inv, w1 = e1 * inv;
        wsm[lane]      = w0;
        wsm[lane + 32] = w1;
        uint32_t bal0 = __ballot_sync(0xffffffffu, w0 > 1e-10f);
        uint32_t bal1 = __ballot_sync(0xffffffffu, w1 > 1e-10f);
        int c0 = __popc(bal0);
        if (w0 > 1e-10f) actsm[__popc(bal0 & ((1u << lane) - 1u))] = lane;
        if (w1 > 1e-10f) actsm[c0 + __popc(bal1 & ((1u << lane) - 1u))] = lane + 32;
        if (lane == 0) {
            nactsm = c0 + __popc(bal1);
            float z = mraw * sig_scale[0] + sig_shift[0];
            swsm = 1.f / (1.f + expf(-z));
        }
    }
    __syncthreads();

    int nact = nactsm;
    float4 acc = make_float4(0.f, 0.f, 0.f, 0.f);
    const float4* pb = (const float4*)(p + (size_t)b * KK * DIN);
    for (int j = 0; j < nact; j++) {
        int k = actsm[j];
        float w = wsm[k];
        float4 v = pb[k * 192 + tid];
        acc.x += w * v.x; acc.y += w * v.y; acc.z += w * v.z; acc.w += w * v.w;
    }
    ((float4*)buf)[tid] = acc;
    __syncthreads();

    // Combined channel mix: out = x*(1-sw) + (Wc·ws + bc)*sw
    int o = tid / 64;
    int hw = (tid % 64) * 4;
    float wc0 = g_Wc[o * 3 + 0], wc1 = g_Wc[o * 3 + 1], wc2 = g_Wc[o * 3 + 2];
    float bcc = g_bc[o];
    float sw = swsm;
    float4 xv = ((const float4*)(x + (size_t)b * DIN))[tid];
    float pa0 = wc0 * buf[hw + 0] + wc1 * buf[256 + hw + 0] + wc2 * buf[512 + hw + 0] + bcc;
    float pa1 = wc0 * buf[hw + 1] + wc1 * buf[256 + hw + 1] + wc2 * buf[512 + hw + 1] + bcc;
    float pa2 = wc0 * buf[hw + 2] + wc1 * buf[256 + hw + 2] + wc2 * buf[512 + hw + 2] + bcc;
    float pa3 = wc0 * buf[hw + 3] + wc1 * buf[256 + hw + 3] + wc2 * buf[512 + hw + 3] + bcc;
    float4 ov;
    ov.x = xv.x * (1.f - sw) + pa0 * sw;
    ov.y = xv.y * (1.f - sw) + pa1 * sw;
    ov.z = xv.z * (1.f - sw) + pa2 * sw;
    ov.w = xv.w * (1.f - sw) + pa3 * sw;
    ((float4*)(out + (size_t)b * DIN))[tid] = ov;
}

// ---------------- launch ----------------
extern "C" void kernel_launch(void* const* d_in, const int* in_sizes, int n_in,
                              void* d_out, int out_size) {
    const float* x         = (const float*)d_in[0];
    const float* p         = (const float*)d_in[1];
    const float* x_im      = (const float*)d_in[2];
    const float* p_im      = (const float*)d_in[3];
    const float* Wtheta    = (const float*)d_in[4];
    const float* btheta    = (const float*)d_in[5];
    const float* Wphi      = (const float*)d_in[6];
    const float* bphi      = (const float*)d_in[7];
    const float* Wg        = (const float*)d_in[8];
    const float* bg        = (const float*)d_in[9];
    const float* Wo        = (const float*)d_in[10];
    const float* bo        = (const float*)d_in[11];
    const float* sig_scale = (const float*)d_in[12];
    const float* sig_shift = (const float*)d_in[13];
    float* out = (float*)d_out;

    cudaFuncSetAttribute(kernB, cudaFuncAttributeMaxDynamicSharedMemorySize, SMEMB_TOTAL);

    kernEF<<<433, 256>>>(Wphi, Wtheta, Wg, bg, Wo, bo);
    kernA<<<BB / 16, 256>>>(x_im, btheta);
    kernB<<<MROWS / 128, 256, SMEMB_TOTAL>>>(p_im, bphi);
    kernRP<<<1024, 256>>>(p_im);
    kernF<<<64, 256>>>(bphi);
    kernD<<<BB, 192>>>(x, p, sig_scale, sig_shift, out);
}